// round 1
// baseline (speedup 1.0000x reference)
#include <cuda_runtime.h>
#include <math.h>

#define S_LEN 2048
#define DIMN  2048
#define NH    16
#define NKV   4
#define HD    128
#define ROWS  4096   // B*S

// ---------------- scratch (device globals; no allocation allowed) ----------
__device__ float g_xn[ROWS * DIMN];   // LN output (reused for LN1 and LN2)
__device__ float g_q [ROWS * DIMN];   // (B,S,16,128)
__device__ float g_k [ROWS * 512];    // (B,S,4,128)
__device__ float g_v [ROWS * 512];    // (B,S,4,128)
__device__ float g_ao[ROWS * DIMN];   // attention output (B,S,16,128)
__device__ int   g_cs[2 * S_LEN];     // per-batch inclusive cumsum of labels

// ---------------- cumsum of seizure labels (per batch) ---------------------
__global__ void cumsum_kernel(const int* __restrict__ labels) {
    __shared__ int bufA[S_LEN], bufB[S_LEN];
    int b = blockIdx.x;
    for (int i = threadIdx.x; i < S_LEN; i += blockDim.x)
        bufA[i] = labels[b * S_LEN + i];
    __syncthreads();
    int* src = bufA; int* dst = bufB;
    for (int off = 1; off < S_LEN; off <<= 1) {
        for (int i = threadIdx.x; i < S_LEN; i += blockDim.x)
            dst[i] = src[i] + (i >= off ? src[i - off] : 0);
        __syncthreads();
        int* t = src; src = dst; dst = t;
    }
    for (int i = threadIdx.x; i < S_LEN; i += blockDim.x)
        g_cs[b * S_LEN + i] = src[i];
}

// ---------------- layernorm (one block per row, 256 threads) ---------------
__global__ void ln_kernel(const float* __restrict__ in, const float* __restrict__ w,
                          const float* __restrict__ bvec, float* __restrict__ out) {
    int row = blockIdx.x;
    const float* x = in + (size_t)row * DIMN;
    float* o = out + (size_t)row * DIMN;
    int tid = threadIdx.x;

    float4 v0 = *(const float4*)(x + tid * 4);
    float4 v1 = *(const float4*)(x + 1024 + tid * 4);
    float s  = v0.x + v0.y + v0.z + v0.w + v1.x + v1.y + v1.z + v1.w;
    float ss = v0.x*v0.x + v0.y*v0.y + v0.z*v0.z + v0.w*v0.w
             + v1.x*v1.x + v1.y*v1.y + v1.z*v1.z + v1.w*v1.w;
    #pragma unroll
    for (int off = 16; off; off >>= 1) {
        s  += __shfl_xor_sync(0xffffffffu, s,  off);
        ss += __shfl_xor_sync(0xffffffffu, ss, off);
    }
    __shared__ float rs[8], rss[8];
    __shared__ float s_mu, s_rstd;
    int wid = tid >> 5, lane = tid & 31;
    if (!lane) { rs[wid] = s; rss[wid] = ss; }
    __syncthreads();
    if (tid == 0) {
        float S = 0.f, SS = 0.f;
        #pragma unroll
        for (int i = 0; i < 8; ++i) { S += rs[i]; SS += rss[i]; }
        float mu = S / DIMN;
        s_mu = mu;
        s_rstd = rsqrtf(SS / DIMN - mu * mu + 1e-5f);
    }
    __syncthreads();
    float mu = s_mu, rstd = s_rstd;

    float4 w0 = *(const float4*)(w + tid * 4);
    float4 b0 = *(const float4*)(bvec + tid * 4);
    float4 r0;
    r0.x = (v0.x - mu) * rstd * w0.x + b0.x;
    r0.y = (v0.y - mu) * rstd * w0.y + b0.y;
    r0.z = (v0.z - mu) * rstd * w0.z + b0.z;
    r0.w = (v0.w - mu) * rstd * w0.w + b0.w;
    *(float4*)(o + tid * 4) = r0;

    float4 w1 = *(const float4*)(w + 1024 + tid * 4);
    float4 b1 = *(const float4*)(bvec + 1024 + tid * 4);
    float4 r1;
    r1.x = (v1.x - mu) * rstd * w1.x + b1.x;
    r1.y = (v1.y - mu) * rstd * w1.y + b1.y;
    r1.z = (v1.z - mu) * rstd * w1.z + b1.z;
    r1.w = (v1.w - mu) * rstd * w1.w + b1.w;
    *(float4*)(o + 1024 + tid * 4) = r1;
}

// ---------------- SGEMM: C[M,N] = A[M,K] * B[N,K]^T  (both K-major) --------
__global__ __launch_bounds__(256, 2)
void sgemm_nt(const float* __restrict__ A, const float* __restrict__ B,
              float* __restrict__ C, int M, int N, int K) {
    __shared__ float As[16][128];
    __shared__ float Bs[16][128];
    int tid = threadIdx.x;
    int tr = tid >> 4, tc = tid & 15;
    const float* Ab = A + (size_t)(blockIdx.y * 128) * K;
    const float* Bb = B + (size_t)(blockIdx.x * 128) * K;

    float acc[8][8];
    #pragma unroll
    for (int i = 0; i < 8; ++i)
        #pragma unroll
        for (int j = 0; j < 8; ++j) acc[i][j] = 0.f;

    for (int k0 = 0; k0 < K; k0 += 16) {
        #pragma unroll
        for (int it = 0; it < 2; ++it) {
            int lin = it * 256 + tid;     // 0..511
            int r = lin >> 2;             // 0..127
            int c = (lin & 3) << 2;       // 0,4,8,12
            float4 va = *(const float4*)(Ab + (size_t)r * K + k0 + c);
            As[c + 0][r] = va.x; As[c + 1][r] = va.y;
            As[c + 2][r] = va.z; As[c + 3][r] = va.w;
            float4 vb = *(const float4*)(Bb + (size_t)r * K + k0 + c);
            Bs[c + 0][r] = vb.x; Bs[c + 1][r] = vb.y;
            Bs[c + 2][r] = vb.z; Bs[c + 3][r] = vb.w;
        }
        __syncthreads();
        #pragma unroll
        for (int k = 0; k < 16; ++k) {
            float ar[8], br[8];
            *(float4*)(ar)     = *(const float4*)&As[k][tr * 8];
            *(float4*)(ar + 4) = *(const float4*)&As[k][tr * 8 + 4];
            *(float4*)(br)     = *(const float4*)&Bs[k][tc * 8];
            *(float4*)(br + 4) = *(const float4*)&Bs[k][tc * 8 + 4];
            #pragma unroll
            for (int i = 0; i < 8; ++i)
                #pragma unroll
                for (int j = 0; j < 8; ++j)
                    acc[i][j] += ar[i] * br[j];
        }
        __syncthreads();
    }

    float* Cb = C + (size_t)(blockIdx.y * 128 + tr * 8) * N + blockIdx.x * 128 + tc * 8;
    #pragma unroll
    for (int i = 0; i < 8; ++i) {
        float4 o0 = make_float4(acc[i][0], acc[i][1], acc[i][2], acc[i][3]);
        float4 o1 = make_float4(acc[i][4], acc[i][5], acc[i][6], acc[i][7]);
        *(float4*)(Cb + (size_t)i * N)     = o0;
        *(float4*)(Cb + (size_t)i * N + 4) = o1;
    }
}

// ---------------- RoPE (in place) ------------------------------------------
__global__ void rope_kernel(float* __restrict__ x, const float* __restrict__ fr,
                            int H, int total) {
    int idx = blockIdx.x * blockDim.x + threadIdx.x;
    if (idx >= total) return;
    int i  = idx & 63;
    int h  = (idx >> 6) % H;
    int bs = idx / (64 * H);
    int s  = bs & (S_LEN - 1);
    float c  = fr[(s * 64 + i) * 2 + 0];
    float sn = fr[(s * 64 + i) * 2 + 1];
    float* p = x + ((size_t)bs * H + h) * HD + 2 * i;
    float xr = p[0], xi = p[1];
    p[0] = xr * c - xi * sn;
    p[1] = xr * sn + xi * c;
}

// ---------------- flash attention (causal + pre-ictal bias) ----------------
// grid: (S/64, NH, B), 256 threads. Dynamic smem ~113KB.
__global__ __launch_bounds__(256, 1)
void attn_kernel() {
    extern __shared__ float smf[];
    float* Qt = smf;                  // [128][64] transposed (d, m)
    float* Kt = Qt + 128 * 64;        // [128][64] transposed (d, n)
    float* Vs = Kt + 128 * 64;        // [64][128]
    float* Ps = Vs + 64 * 128;        // [64][68] transposed probs (n, m), pad 4

    const int tid = threadIdx.x;
    const int ty = tid >> 4, tx = tid & 15;
    const int q0 = blockIdx.x * 64;
    const int h  = blockIdx.y;
    const int b  = blockIdx.z;
    const int kvh = h >> 2;

    const float scale = 0.08838834764831845f;  // 1/sqrt(128)

    // load Q tile transposed, pre-scaled
    #pragma unroll
    for (int it = 0; it < 8; ++it) {
        int lin = it * 256 + tid;
        int m = lin >> 5, c4 = (lin & 31) << 2;
        float4 v = *(const float4*)(g_q + (((size_t)(b * S_LEN + q0 + m)) * NH + h) * HD + c4);
        Qt[(c4 + 0) * 64 + m] = v.x * scale;
        Qt[(c4 + 1) * 64 + m] = v.y * scale;
        Qt[(c4 + 2) * 64 + m] = v.z * scale;
        Qt[(c4 + 3) * 64 + m] = v.w * scale;
    }

    int csq[4];
    #pragma unroll
    for (int i = 0; i < 4; ++i) {
        int qg = q0 + ty * 4 + i;
        csq[i] = (qg > 0) ? g_cs[b * S_LEN + qg - 1] : 0;
    }

    float o[4][8];
    #pragma unroll
    for (int i = 0; i < 4; ++i)
        #pragma unroll
        for (int j = 0; j < 8; ++j) o[i][j] = 0.f;
    float mrow[4] = {-1e30f, -1e30f, -1e30f, -1e30f};
    float lrow[4] = {0.f, 0.f, 0.f, 0.f};

    const int nk = q0 + 64;  // causal: k0 <= q0
    for (int k0 = 0; k0 < nk; k0 += 64) {
        __syncthreads();   // previous PV done; also covers Q-load on first iter
        #pragma unroll
        for (int it = 0; it < 8; ++it) {
            int lin = it * 256 + tid;
            int n = lin >> 5, c4 = (lin & 31) << 2;
            size_t kidx = (((size_t)(b * S_LEN + k0 + n)) * NKV + kvh) * HD + c4;
            float4 kv = *(const float4*)(g_k + kidx);
            Kt[(c4 + 0) * 64 + n] = kv.x;
            Kt[(c4 + 1) * 64 + n] = kv.y;
            Kt[(c4 + 2) * 64 + n] = kv.z;
            Kt[(c4 + 3) * 64 + n] = kv.w;
            *(float4*)(Vs + n * 128 + c4) = *(const float4*)(g_v + kidx);
        }
        __syncthreads();

        // S = Q K^T (register-tiled 4x4 per thread)
        float acc[4][4];
        #pragma unroll
        for (int i = 0; i < 4; ++i)
            #pragma unroll
            for (int j = 0; j < 4; ++j) acc[i][j] = 0.f;
        #pragma unroll 8
        for (int d = 0; d < 128; ++d) {
            float4 a4 = *(const float4*)(Qt + d * 64 + ty * 4);
            float4 b4 = *(const float4*)(Kt + d * 64 + tx * 4);
            float av[4] = {a4.x, a4.y, a4.z, a4.w};
            float bv[4] = {b4.x, b4.y, b4.z, b4.w};
            #pragma unroll
            for (int i = 0; i < 4; ++i)
                #pragma unroll
                for (int j = 0; j < 4; ++j)
                    acc[i][j] += av[i] * bv[j];
        }

        // bias + causal mask
        int csk[4];
        #pragma unroll
        for (int j = 0; j < 4; ++j) {
            int kg = k0 + tx * 4 + j;
            int bi = kg + 10; if (bi > S_LEN - 1) bi = S_LEN - 1;
            csk[j] = g_cs[b * S_LEN + bi];
        }
        #pragma unroll
        for (int i = 0; i < 4; ++i) {
            int qg = q0 + ty * 4 + i;
            #pragma unroll
            for (int j = 0; j < 4; ++j) {
                int kg = k0 + tx * 4 + j;
                float v = acc[i][j];
                if (kg + 10 >= qg && (csk[j] - csq[i]) > 0) v += 2.0f;
                if (kg > qg) v = -1e9f;
                acc[i][j] = v;
            }
        }

        // online softmax (rows split across 16 tx threads)
        #pragma unroll
        for (int i = 0; i < 4; ++i) {
            float rm = fmaxf(fmaxf(acc[i][0], acc[i][1]), fmaxf(acc[i][2], acc[i][3]));
            #pragma unroll
            for (int off = 8; off; off >>= 1)
                rm = fmaxf(rm, __shfl_xor_sync(0xffffffffu, rm, off, 16));
            float mnew = fmaxf(mrow[i], rm);
            float alpha = __expf(mrow[i] - mnew);
            float rs = 0.f;
            #pragma unroll
            for (int j = 0; j < 4; ++j) {
                float p = __expf(acc[i][j] - mnew);
                acc[i][j] = p;
                rs += p;
            }
            #pragma unroll
            for (int off = 8; off; off >>= 1)
                rs += __shfl_xor_sync(0xffffffffu, rs, off, 16);
            lrow[i] = lrow[i] * alpha + rs;
            mrow[i] = mnew;
            #pragma unroll
            for (int j = 0; j < 8; ++j) o[i][j] *= alpha;
        }

        // stash P transposed: Ps[n][m]
        #pragma unroll
        for (int i = 0; i < 4; ++i)
            #pragma unroll
            for (int j = 0; j < 4; ++j)
                Ps[(tx * 4 + j) * 68 + ty * 4 + i] = acc[i][j];
        __syncthreads();

        // O += P V
        #pragma unroll 4
        for (int k = 0; k < 64; ++k) {
            float4 a4 = *(const float4*)(Ps + k * 68 + ty * 4);
            float4 b0 = *(const float4*)(Vs + k * 128 + tx * 8);
            float4 b1 = *(const float4*)(Vs + k * 128 + tx * 8 + 4);
            float av[4] = {a4.x, a4.y, a4.z, a4.w};
            float bv[8] = {b0.x, b0.y, b0.z, b0.w, b1.x, b1.y, b1.z, b1.w};
            #pragma unroll
            for (int i = 0; i < 4; ++i)
                #pragma unroll
                for (int j = 0; j < 8; ++j)
                    o[i][j] += av[i] * bv[j];
        }
    }

    // epilogue: normalize and store (B,S,NH,HD)
    #pragma unroll
    for (int i = 0; i < 4; ++i) {
        float inv = 1.0f / lrow[i];
        float4 r0 = make_float4(o[i][0] * inv, o[i][1] * inv, o[i][2] * inv, o[i][3] * inv);
        float4 r1 = make_float4(o[i][4] * inv, o[i][5] * inv, o[i][6] * inv, o[i][7] * inv);
        size_t base = (((size_t)(b * S_LEN + q0 + ty * 4 + i)) * NH + h) * HD + tx * 8;
        *(float4*)(g_ao + base)     = r0;
        *(float4*)(g_ao + base + 4) = r1;
    }
}

// ---------------- launch ----------------------------------------------------
extern "C" void kernel_launch(void* const* d_in, const int* in_sizes, int n_in,
                              void* d_out, int out_size) {
    const float* x      = (const float*)d_in[0];
    const float* freqs  = (const float*)d_in[2];
    const int*   labels = (const int*)d_in[4];
    const float* wq     = (const float*)d_in[5];
    const float* wk     = (const float*)d_in[6];
    const float* wv     = (const float*)d_in[7];
    const float* wo     = (const float*)d_in[8];
    const float* ln1w   = (const float*)d_in[9];
    const float* ln1b   = (const float*)d_in[10];
    const float* ln2w   = (const float*)d_in[11];
    const float* ln2b   = (const float*)d_in[12];
    float* out = (float*)d_out;

    float *xn, *q, *k, *v, *ao;
    cudaGetSymbolAddress((void**)&xn, g_xn);
    cudaGetSymbolAddress((void**)&q,  g_q);
    cudaGetSymbolAddress((void**)&k,  g_k);
    cudaGetSymbolAddress((void**)&v,  g_v);
    cudaGetSymbolAddress((void**)&ao, g_ao);

    cumsum_kernel<<<2, 1024>>>(labels);
    ln_kernel<<<ROWS, 256>>>(x, ln1w, ln1b, xn);

    dim3 gq(DIMN / 128, ROWS / 128);   // 16 x 32
    dim3 gkv(512 / 128, ROWS / 128);   // 4 x 32
    sgemm_nt<<<gq, 256>>>(xn, wq, q, ROWS, DIMN, DIMN);
    sgemm_nt<<<gkv, 256>>>(xn, wk, k, ROWS, 512, DIMN);
    sgemm_nt<<<gkv, 256>>>(xn, wv, v, ROWS, 512, DIMN);

    rope_kernel<<<(ROWS * NH * 64) / 256, 256>>>(q, freqs, NH, ROWS * NH * 64);
    rope_kernel<<<(ROWS * NKV * 64) / 256, 256>>>(k, freqs, NKV, ROWS * NKV * 64);

    size_t attn_smem = (size_t)(128 * 64 * 2 + 64 * 128 + 64 * 68) * sizeof(float);
    cudaFuncSetAttribute(attn_kernel, cudaFuncAttributeMaxDynamicSharedMemorySize,
                         (int)attn_smem);
    attn_kernel<<<dim3(S_LEN / 64, NH, 2), 256, attn_smem>>>();

    ln_kernel<<<ROWS, 256>>>(ao, ln2w, ln2b, xn);
    sgemm_nt<<<gq, 256>>>(xn, wo, out, ROWS, DIMN, DIMN);
}

// round 3
// speedup vs baseline: 1.5380x; 1.5380x over previous
#include <cuda_runtime.h>
#include <cuda_bf16.h>
#include <math.h>
#include <stdint.h>

#define S_LEN 2048
#define DIMN  2048
#define NH    16
#define NKV   4
#define HD    128
#define ROWS  4096   // B*S

// ---------------- scratch (device globals; no allocation allowed) ----------
__device__ __nv_bfloat16 g_xn_h[ROWS * DIMN];
__device__ __nv_bfloat16 g_xn_l[ROWS * DIMN];
__device__ __nv_bfloat16 g_wq_h[DIMN * DIMN];
__device__ __nv_bfloat16 g_wq_l[DIMN * DIMN];
__device__ __nv_bfloat16 g_wk_h[512 * DIMN];
__device__ __nv_bfloat16 g_wk_l[512 * DIMN];
__device__ __nv_bfloat16 g_wv_h[512 * DIMN];
__device__ __nv_bfloat16 g_wv_l[512 * DIMN];
__device__ __nv_bfloat16 g_wo_h[DIMN * DIMN];
__device__ __nv_bfloat16 g_wo_l[DIMN * DIMN];
__device__ float g_q [ROWS * DIMN];   // (B,S,16,128)
__device__ float g_k [ROWS * 512];    // (B,S,4,128)
__device__ float g_v [ROWS * 512];    // (B,S,4,128)
__device__ float g_ao[ROWS * DIMN];   // attention output (B,S,16,128)
__device__ int   g_cs[2 * S_LEN];     // per-batch inclusive cumsum of labels

// ---------------- helpers ----------------------------------------------------
__device__ __forceinline__ uint32_t smem_to_u32(const void* p) {
    uint32_t a;
    asm("{ .reg .u64 t; cvta.to.shared.u64 t, %1; cvt.u32.u64 %0, t; }" : "=r"(a) : "l"(p));
    return a;
}

__device__ __forceinline__ void ldmx4(uint32_t* r, uint32_t addr) {
    asm volatile("ldmatrix.sync.aligned.m8n8.x4.shared.b16 {%0,%1,%2,%3}, [%4];"
        : "=r"(r[0]), "=r"(r[1]), "=r"(r[2]), "=r"(r[3]) : "r"(addr));
}
__device__ __forceinline__ void ldmx2(uint32_t* r, uint32_t addr) {
    asm volatile("ldmatrix.sync.aligned.m8n8.x2.shared.b16 {%0,%1}, [%2];"
        : "=r"(r[0]), "=r"(r[1]) : "r"(addr));
}
__device__ __forceinline__ void mma16816(float* c, const uint32_t* a, const uint32_t* b) {
    asm volatile(
        "mma.sync.aligned.m16n8k16.row.col.f32.bf16.bf16.f32 "
        "{%0,%1,%2,%3}, {%4,%5,%6,%7}, {%8,%9}, {%0,%1,%2,%3};"
        : "+f"(c[0]), "+f"(c[1]), "+f"(c[2]), "+f"(c[3])
        : "r"(a[0]), "r"(a[1]), "r"(a[2]), "r"(a[3]), "r"(b[0]), "r"(b[1]));
}

// ---------------- cumsum of seizure labels (per batch) ---------------------
__global__ void cumsum_kernel(const int* __restrict__ labels) {
    __shared__ int bufA[S_LEN], bufB[S_LEN];
    int b = blockIdx.x;
    for (int i = threadIdx.x; i < S_LEN; i += blockDim.x)
        bufA[i] = labels[b * S_LEN + i];
    __syncthreads();
    int* src = bufA; int* dst = bufB;
    for (int off = 1; off < S_LEN; off <<= 1) {
        for (int i = threadIdx.x; i < S_LEN; i += blockDim.x)
            dst[i] = src[i] + (i >= off ? src[i - off] : 0);
        __syncthreads();
        int* t = src; src = dst; dst = t;
    }
    for (int i = threadIdx.x; i < S_LEN; i += blockDim.x)
        g_cs[b * S_LEN + i] = src[i];
}

// ---------------- bf16 split helpers ---------------------------------------
__device__ __forceinline__ void split4(float4 v, uint32_t& h01, uint32_t& h23,
                                       uint32_t& l01, uint32_t& l23) {
    float f[4] = {v.x, v.y, v.z, v.w};
    __nv_bfloat16 h[4], l[4];
    #pragma unroll
    for (int i = 0; i < 4; ++i) {
        h[i] = __float2bfloat16(f[i]);
        l[i] = __float2bfloat16(f[i] - __bfloat162float(h[i]));
    }
    __nv_bfloat162 H0 = {h[0], h[1]}, H1 = {h[2], h[3]};
    __nv_bfloat162 L0 = {l[0], l[1]}, L1 = {l[2], l[3]};
    h01 = *(uint32_t*)&H0; h23 = *(uint32_t*)&H1;
    l01 = *(uint32_t*)&L0; l23 = *(uint32_t*)&L1;
}

__global__ void split_kernel(const float* __restrict__ in,
                             __nv_bfloat16* __restrict__ hi,
                             __nv_bfloat16* __restrict__ lo, int n4) {
    int i = blockIdx.x * blockDim.x + threadIdx.x;
    if (i >= n4) return;
    float4 v = ((const float4*)in)[i];
    uint32_t h01, h23, l01, l23;
    split4(v, h01, h23, l01, l23);
    *(uint2*)(hi + (size_t)i * 4) = make_uint2(h01, h23);
    *(uint2*)(lo + (size_t)i * 4) = make_uint2(l01, l23);
}

// ---------------- layernorm -> bf16 hi/lo -----------------------------------
__global__ void ln_kernel(const float* __restrict__ in, const float* __restrict__ w,
                          const float* __restrict__ bvec,
                          __nv_bfloat16* __restrict__ oh, __nv_bfloat16* __restrict__ ol) {
    int row = blockIdx.x;
    const float* x = in + (size_t)row * DIMN;
    int tid = threadIdx.x;

    float4 v0 = *(const float4*)(x + tid * 4);
    float4 v1 = *(const float4*)(x + 1024 + tid * 4);
    float s  = v0.x + v0.y + v0.z + v0.w + v1.x + v1.y + v1.z + v1.w;
    float ss = v0.x*v0.x + v0.y*v0.y + v0.z*v0.z + v0.w*v0.w
             + v1.x*v1.x + v1.y*v1.y + v1.z*v1.z + v1.w*v1.w;
    #pragma unroll
    for (int off = 16; off; off >>= 1) {
        s  += __shfl_xor_sync(0xffffffffu, s,  off);
        ss += __shfl_xor_sync(0xffffffffu, ss, off);
    }
    __shared__ float rs[8], rss[8];
    __shared__ float s_mu, s_rstd;
    int wid = tid >> 5, lane = tid & 31;
    if (!lane) { rs[wid] = s; rss[wid] = ss; }
    __syncthreads();
    if (tid == 0) {
        float S = 0.f, SS = 0.f;
        #pragma unroll
        for (int i = 0; i < 8; ++i) { S += rs[i]; SS += rss[i]; }
        float mu = S / DIMN;
        s_mu = mu;
        s_rstd = rsqrtf(SS / DIMN - mu * mu + 1e-5f);
    }
    __syncthreads();
    float mu = s_mu, rstd = s_rstd;

    size_t base = (size_t)row * DIMN;
    #pragma unroll
    for (int half = 0; half < 2; ++half) {
        int off = half * 1024 + tid * 4;
        float4 v = half ? v1 : v0;
        float4 w4 = *(const float4*)(w + off);
        float4 b4 = *(const float4*)(bvec + off);
        float4 r;
        r.x = (v.x - mu) * rstd * w4.x + b4.x;
        r.y = (v.y - mu) * rstd * w4.y + b4.y;
        r.z = (v.z - mu) * rstd * w4.z + b4.z;
        r.w = (v.w - mu) * rstd * w4.w + b4.w;
        uint32_t h01, h23, l01, l23;
        split4(r, h01, h23, l01, l23);
        *(uint2*)(oh + base + off) = make_uint2(h01, h23);
        *(uint2*)(ol + base + off) = make_uint2(l01, l23);
    }
}

// ---------------- mma.sync GEMM: C[M,N] = A[M,K] * B[N,K]^T -----------------
// bf16-split: D += Ah Bh^T + Ah Bl^T + Al Bh^T, fp32 accum.
// CTA tile 128x128x32; 8 warps (2x4), warp tile 64x32; cp.async double-buffer.
#define PITCH 80            // smem bytes per 32-elem bf16 row (64 data + 16 pad)
#define TILE_B (128 * PITCH)   // 10240 bytes per operand tile
#define STAGE_B (4 * TILE_B)   // 40960 bytes per stage

__device__ __forceinline__ void cp_tile(uint32_t sdst, const __nv_bfloat16* __restrict__ g,
                                        int row0, int K, int k0) {
    int tid = threadIdx.x;
    const char* gb = (const char*)(g + (size_t)row0 * K + k0);
    size_t rb = (size_t)K * 2;
    #pragma unroll
    for (int j = 0; j < 2; ++j) {
        int lin = j * 256 + tid;
        int r = lin >> 2, c = lin & 3;
        uint32_t d = sdst + r * PITCH + c * 16;
        const char* s = gb + (size_t)r * rb + c * 16;
        asm volatile("cp.async.ca.shared.global [%0], [%1], 16;" :: "r"(d), "l"(s));
    }
}

__global__ __launch_bounds__(256)
void mma_gemm(const __nv_bfloat16* __restrict__ Ah, const __nv_bfloat16* __restrict__ Al,
              const __nv_bfloat16* __restrict__ Bh, const __nv_bfloat16* __restrict__ Bl,
              float* __restrict__ C, int M, int N, int K) {
    extern __shared__ char sm[];
    uint32_t sb = smem_to_u32(sm);
    int tid = threadIdx.x, lane = tid & 31, wid = tid >> 5;
    int wm = wid & 1, wn = wid >> 1;
    int row0 = blockIdx.y * 128, col0 = blockIdx.x * 128;

    float acc[4][4][4];
    #pragma unroll
    for (int i = 0; i < 4; ++i)
        #pragma unroll
        for (int j = 0; j < 4; ++j)
            #pragma unroll
            for (int q = 0; q < 4; ++q) acc[i][j][q] = 0.f;

    const int nst = K >> 5;

    cp_tile(sb,              Ah, row0, K, 0);
    cp_tile(sb + TILE_B,     Al, row0, K, 0);
    cp_tile(sb + 2 * TILE_B, Bh, col0, K, 0);
    cp_tile(sb + 3 * TILE_B, Bl, col0, K, 0);
    asm volatile("cp.async.commit_group;" ::: "memory");

    for (int i = 0; i < nst; ++i) {
        if (i + 1 < nst) {
            uint32_t st = sb + ((i + 1) & 1) * STAGE_B;
            int k0 = (i + 1) << 5;
            cp_tile(st,              Ah, row0, K, k0);
            cp_tile(st + TILE_B,     Al, row0, K, k0);
            cp_tile(st + 2 * TILE_B, Bh, col0, K, k0);
            cp_tile(st + 3 * TILE_B, Bl, col0, K, k0);
            asm volatile("cp.async.commit_group;" ::: "memory");
            asm volatile("cp.async.wait_group 1;" ::: "memory");
        } else {
            asm volatile("cp.async.wait_group 0;" ::: "memory");
        }
        __syncthreads();

        uint32_t st = sb + (i & 1) * STAGE_B;
        #pragma unroll
        for (int ks = 0; ks < 2; ++ks) {
            uint32_t ah[4][4], al[4][4], bh[4][2], bl[4][2];
            uint32_t abase = st + (wm * 64 + (lane & 15)) * PITCH
                           + (ks * 2 + (lane >> 4)) * 16;
            #pragma unroll
            for (int mi = 0; mi < 4; ++mi) ldmx4(ah[mi], abase + mi * 16 * PITCH);
            #pragma unroll
            for (int mi = 0; mi < 4; ++mi) ldmx4(al[mi], abase + TILE_B + mi * 16 * PITCH);
            uint32_t bbase = st + 2 * TILE_B + (wn * 32 + (lane & 7)) * PITCH
                           + ((lane >> 3) & 1) * 16 + ks * 32;
            #pragma unroll
            for (int ni = 0; ni < 4; ++ni) ldmx2(bh[ni], bbase + ni * 8 * PITCH);
            #pragma unroll
            for (int ni = 0; ni < 4; ++ni) ldmx2(bl[ni], bbase + TILE_B + ni * 8 * PITCH);
            #pragma unroll
            for (int mi = 0; mi < 4; ++mi)
                #pragma unroll
                for (int ni = 0; ni < 4; ++ni) {
                    mma16816(acc[mi][ni], ah[mi], bh[ni]);
                    mma16816(acc[mi][ni], ah[mi], bl[ni]);
                    mma16816(acc[mi][ni], al[mi], bh[ni]);
                }
        }
        __syncthreads();
    }

    // epilogue: c0,c1 -> (m = lane/4, n = (lane%4)*2), c2,c3 -> m+8
    int mrow = row0 + wm * 64 + (lane >> 2);
    int ncol = col0 + wn * 32 + (lane & 3) * 2;
    #pragma unroll
    for (int mi = 0; mi < 4; ++mi)
        #pragma unroll
        for (int ni = 0; ni < 4; ++ni) {
            float* p0 = C + (size_t)(mrow + mi * 16) * N + ncol + ni * 8;
            float* p1 = C + (size_t)(mrow + mi * 16 + 8) * N + ncol + ni * 8;
            *(float2*)p0 = make_float2(acc[mi][ni][0], acc[mi][ni][1]);
            *(float2*)p1 = make_float2(acc[mi][ni][2], acc[mi][ni][3]);
        }
}

// ---------------- RoPE (in place) ------------------------------------------
__global__ void rope_kernel(float* __restrict__ x, const float* __restrict__ fr,
                            int H, int total) {
    int idx = blockIdx.x * blockDim.x + threadIdx.x;
    if (idx >= total) return;
    int i  = idx & 63;
    int h  = (idx >> 6) % H;
    int bs = idx / (64 * H);
    int s  = bs & (S_LEN - 1);
    float c  = fr[(s * 64 + i) * 2 + 0];
    float sn = fr[(s * 64 + i) * 2 + 1];
    float* p = x + ((size_t)bs * H + h) * HD + 2 * i;
    float xr = p[0], xi = p[1];
    p[0] = xr * c - xi * sn;
    p[1] = xr * sn + xi * c;
}

// ---------------- flash attention (causal + pre-ictal bias) ----------------
__global__ __launch_bounds__(256, 1)
void attn_kernel() {
    extern __shared__ float smf[];
    float* Qt = smf;                  // [128][64]
    float* Kt = Qt + 128 * 64;        // [128][64]
    float* Vs = Kt + 128 * 64;        // [64][128]
    float* Ps = Vs + 64 * 128;        // [64][68]

    const int tid = threadIdx.x;
    const int ty = tid >> 4, tx = tid & 15;
    const int q0 = blockIdx.x * 64;
    const int h  = blockIdx.y;
    const int b  = blockIdx.z;
    const int kvh = h >> 2;

    const float scale = 0.08838834764831845f;

    #pragma unroll
    for (int it = 0; it < 8; ++it) {
        int lin = it * 256 + tid;
        int m = lin >> 5, c4 = (lin & 31) << 2;
        float4 v = *(const float4*)(g_q + (((size_t)(b * S_LEN + q0 + m)) * NH + h) * HD + c4);
        Qt[(c4 + 0) * 64 + m] = v.x * scale;
        Qt[(c4 + 1) * 64 + m] = v.y * scale;
        Qt[(c4 + 2) * 64 + m] = v.z * scale;
        Qt[(c4 + 3) * 64 + m] = v.w * scale;
    }

    int csq[4];
    #pragma unroll
    for (int i = 0; i < 4; ++i) {
        int qg = q0 + ty * 4 + i;
        csq[i] = (qg > 0) ? g_cs[b * S_LEN + qg - 1] : 0;
    }

    float o[4][8];
    #pragma unroll
    for (int i = 0; i < 4; ++i)
        #pragma unroll
        for (int j = 0; j < 8; ++j) o[i][j] = 0.f;
    float mrow[4] = {-1e30f, -1e30f, -1e30f, -1e30f};
    float lrow[4] = {0.f, 0.f, 0.f, 0.f};

    const int nk = q0 + 64;
    for (int k0 = 0; k0 < nk; k0 += 64) {
        __syncthreads();
        #pragma unroll
        for (int it = 0; it < 8; ++it) {
            int lin = it * 256 + tid;
            int n = lin >> 5, c4 = (lin & 31) << 2;
            size_t kidx = (((size_t)(b * S_LEN + k0 + n)) * NKV + kvh) * HD + c4;
            float4 kv = *(const float4*)(g_k + kidx);
            Kt[(c4 + 0) * 64 + n] = kv.x;
            Kt[(c4 + 1) * 64 + n] = kv.y;
            Kt[(c4 + 2) * 64 + n] = kv.z;
            Kt[(c4 + 3) * 64 + n] = kv.w;
            *(float4*)(Vs + n * 128 + c4) = *(const float4*)(g_v + kidx);
        }
        __syncthreads();

        float acc[4][4];
        #pragma unroll
        for (int i = 0; i < 4; ++i)
            #pragma unroll
            for (int j = 0; j < 4; ++j) acc[i][j] = 0.f;
        #pragma unroll 8
        for (int d = 0; d < 128; ++d) {
            float4 a4 = *(const float4*)(Qt + d * 64 + ty * 4);
            float4 b4 = *(const float4*)(Kt + d * 64 + tx * 4);
            float av[4] = {a4.x, a4.y, a4.z, a4.w};
            float bv[4] = {b4.x, b4.y, b4.z, b4.w};
            #pragma unroll
            for (int i = 0; i < 4; ++i)
                #pragma unroll
                for (int j = 0; j < 4; ++j)
                    acc[i][j] += av[i] * bv[j];
        }

        int csk[4];
        #pragma unroll
        for (int j = 0; j < 4; ++j) {
            int kg = k0 + tx * 4 + j;
            int bi = kg + 10; if (bi > S_LEN - 1) bi = S_LEN - 1;
            csk[j] = g_cs[b * S_LEN + bi];
        }
        #pragma unroll
        for (int i = 0; i < 4; ++i) {
            int qg = q0 + ty * 4 + i;
            #pragma unroll
            for (int j = 0; j < 4; ++j) {
                int kg = k0 + tx * 4 + j;
                float v = acc[i][j];
                if (kg + 10 >= qg && (csk[j] - csq[i]) > 0) v += 2.0f;
                if (kg > qg) v = -1e9f;
                acc[i][j] = v;
            }
        }

        #pragma unroll
        for (int i = 0; i < 4; ++i) {
            float rm = fmaxf(fmaxf(acc[i][0], acc[i][1]), fmaxf(acc[i][2], acc[i][3]));
            #pragma unroll
            for (int off = 8; off; off >>= 1)
                rm = fmaxf(rm, __shfl_xor_sync(0xffffffffu, rm, off, 16));
            float mnew = fmaxf(mrow[i], rm);
            float alpha = __expf(mrow[i] - mnew);
            float rs = 0.f;
            #pragma unroll
            for (int j = 0; j < 4; ++j) {
                float p = __expf(acc[i][j] - mnew);
                acc[i][j] = p;
                rs += p;
            }
            #pragma unroll
            for (int off = 8; off; off >>= 1)
                rs += __shfl_xor_sync(0xffffffffu, rs, off, 16);
            lrow[i] = lrow[i] * alpha + rs;
            mrow[i] = mnew;
            #pragma unroll
            for (int j = 0; j < 8; ++j) o[i][j] *= alpha;
        }

        #pragma unroll
        for (int i = 0; i < 4; ++i)
            #pragma unroll
            for (int j = 0; j < 4; ++j)
                Ps[(tx * 4 + j) * 68 + ty * 4 + i] = acc[i][j];
        __syncthreads();

        #pragma unroll 4
        for (int k = 0; k < 64; ++k) {
            float4 a4 = *(const float4*)(Ps + k * 68 + ty * 4);
            float4 b0 = *(const float4*)(Vs + k * 128 + tx * 8);
            float4 b1 = *(const float4*)(Vs + k * 128 + tx * 8 + 4);
            float av[4] = {a4.x, a4.y, a4.z, a4.w};
            float bv[8] = {b0.x, b0.y, b0.z, b0.w, b1.x, b1.y, b1.z, b1.w};
            #pragma unroll
            for (int i = 0; i < 4; ++i)
                #pragma unroll
                for (int j = 0; j < 8; ++j)
                    o[i][j] += av[i] * bv[j];
        }
    }

    #pragma unroll
    for (int i = 0; i < 4; ++i) {
        float inv = 1.0f / lrow[i];
        float4 r0 = make_float4(o[i][0] * inv, o[i][1] * inv, o[i][2] * inv, o[i][3] * inv);
        float4 r1 = make_float4(o[i][4] * inv, o[i][5] * inv, o[i][6] * inv, o[i][7] * inv);
        size_t base = (((size_t)(b * S_LEN + q0 + ty * 4 + i)) * NH + h) * HD + tx * 8;
        *(float4*)(g_ao + base)     = r0;
        *(float4*)(g_ao + base + 4) = r1;
    }
}

// ---------------- launch ----------------------------------------------------
extern "C" void kernel_launch(void* const* d_in, const int* in_sizes, int n_in,
                              void* d_out, int out_size) {
    const float* x      = (const float*)d_in[0];
    const float* freqs  = (const float*)d_in[2];
    const int*   labels = (const int*)d_in[4];
    const float* wq     = (const float*)d_in[5];
    const float* wk     = (const float*)d_in[6];
    const float* wv     = (const float*)d_in[7];
    const float* wo     = (const float*)d_in[8];
    const float* ln1w   = (const float*)d_in[9];
    const float* ln1b   = (const float*)d_in[10];
    const float* ln2w   = (const float*)d_in[11];
    const float* ln2b   = (const float*)d_in[12];
    float* out = (float*)d_out;

    __nv_bfloat16 *xnh, *xnl, *wqh, *wql, *wkh, *wkl, *wvh, *wvl, *woh, *wol;
    float *q, *k, *v, *ao;
    cudaGetSymbolAddress((void**)&xnh, g_xn_h);
    cudaGetSymbolAddress((void**)&xnl, g_xn_l);
    cudaGetSymbolAddress((void**)&wqh, g_wq_h);
    cudaGetSymbolAddress((void**)&wql, g_wq_l);
    cudaGetSymbolAddress((void**)&wkh, g_wk_h);
    cudaGetSymbolAddress((void**)&wkl, g_wk_l);
    cudaGetSymbolAddress((void**)&wvh, g_wv_h);
    cudaGetSymbolAddress((void**)&wvl, g_wv_l);
    cudaGetSymbolAddress((void**)&woh, g_wo_h);
    cudaGetSymbolAddress((void**)&wol, g_wo_l);
    cudaGetSymbolAddress((void**)&q,  g_q);
    cudaGetSymbolAddress((void**)&k,  g_k);
    cudaGetSymbolAddress((void**)&v,  g_v);
    cudaGetSymbolAddress((void**)&ao, g_ao);

    cumsum_kernel<<<2, 1024>>>(labels);

    split_kernel<<<(DIMN * DIMN / 4 + 255) / 256, 256>>>(wq, wqh, wql, DIMN * DIMN / 4);
    split_kernel<<<(512 * DIMN / 4 + 255) / 256, 256>>>(wk, wkh, wkl, 512 * DIMN / 4);
    split_kernel<<<(512 * DIMN / 4 + 255) / 256, 256>>>(wv, wvh, wvl, 512 * DIMN / 4);
    split_kernel<<<(DIMN * DIMN / 4 + 255) / 256, 256>>>(wo, woh, wol, DIMN * DIMN / 4);

    ln_kernel<<<ROWS, 256>>>(x, ln1w, ln1b, xnh, xnl);

    size_t gemm_smem = 2 * STAGE_B;  // 81920
    cudaFuncSetAttribute(mma_gemm, cudaFuncAttributeMaxDynamicSharedMemorySize, (int)gemm_smem);

    dim3 gq(DIMN / 128, ROWS / 128);   // 16 x 32
    dim3 gkv(512 / 128, ROWS / 128);   // 4 x 32
    mma_gemm<<<gq, 256, gemm_smem>>>(xnh, xnl, wqh, wql, q, ROWS, DIMN, DIMN);
    mma_gemm<<<gkv, 256, gemm_smem>>>(xnh, xnl, wkh, wkl, k, ROWS, 512, DIMN);
    mma_gemm<<<gkv, 256, gemm_smem>>>(xnh, xnl, wvh, wvl, v, ROWS, 512, DIMN);

    rope_kernel<<<(ROWS * NH * 64) / 256, 256>>>(q, freqs, NH, ROWS * NH * 64);
    rope_kernel<<<(ROWS * NKV * 64) / 256, 256>>>(k, freqs, NKV, ROWS * NKV * 64);

    size_t attn_smem = (size_t)(128 * 64 * 2 + 64 * 128 + 64 * 68) * sizeof(float);
    cudaFuncSetAttribute(attn_kernel, cudaFuncAttributeMaxDynamicSharedMemorySize,
                         (int)attn_smem);
    attn_kernel<<<dim3(S_LEN / 64, NH, 2), 256, attn_smem>>>();

    ln_kernel<<<ROWS, 256>>>(ao, ln2w, ln2b, xnh, xnl);
    mma_gemm<<<gq, 256, gemm_smem>>>(xnh, xnl, woh, wol, out, ROWS, DIMN, DIMN);
}

// round 4
// speedup vs baseline: 3.4419x; 2.2380x over previous
#include <cuda_runtime.h>
#include <cuda_bf16.h>
#include <math.h>
#include <stdint.h>

#define S_LEN 2048
#define DIMN  2048
#define NH    16
#define NKV   4
#define HD    128
#define ROWS  4096   // B*S

// ---------------- scratch (device globals; no allocation allowed) ----------
__device__ __nv_bfloat16 g_xn_h[ROWS * DIMN];
__device__ __nv_bfloat16 g_xn_l[ROWS * DIMN];
__device__ __nv_bfloat16 g_wq_h[DIMN * DIMN];
__device__ __nv_bfloat16 g_wq_l[DIMN * DIMN];
__device__ __nv_bfloat16 g_wk_h[512 * DIMN];
__device__ __nv_bfloat16 g_wk_l[512 * DIMN];
__device__ __nv_bfloat16 g_wv_h[512 * DIMN];
__device__ __nv_bfloat16 g_wv_l[512 * DIMN];
__device__ __nv_bfloat16 g_wo_h[DIMN * DIMN];
__device__ __nv_bfloat16 g_wo_l[DIMN * DIMN];
__device__ float g_q [ROWS * DIMN];   // fp32 GEMM outputs (pre-rope)
__device__ float g_k [ROWS * 512];
__device__ float g_v [ROWS * 512];
__device__ __nv_bfloat16 g_qh[ROWS * DIMN];  // roped+scaled Q hi/lo
__device__ __nv_bfloat16 g_ql[ROWS * DIMN];
__device__ __nv_bfloat16 g_kh[ROWS * 512];   // roped K hi/lo
__device__ __nv_bfloat16 g_kl[ROWS * 512];
__device__ __nv_bfloat16 g_vh[ROWS * 512];   // V hi/lo
__device__ __nv_bfloat16 g_vl[ROWS * 512];
__device__ float g_ao[ROWS * DIMN];   // attention output (B,S,16,128)
__device__ int   g_cs[2 * S_LEN];     // per-batch inclusive cumsum of labels

// ---------------- helpers ----------------------------------------------------
__device__ __forceinline__ uint32_t smem_to_u32(const void* p) {
    uint32_t a;
    asm("{ .reg .u64 t; cvta.to.shared.u64 t, %1; cvt.u32.u64 %0, t; }" : "=r"(a) : "l"(p));
    return a;
}
__device__ __forceinline__ void ldmx4(uint32_t* r, uint32_t addr) {
    asm volatile("ldmatrix.sync.aligned.m8n8.x4.shared.b16 {%0,%1,%2,%3}, [%4];"
        : "=r"(r[0]), "=r"(r[1]), "=r"(r[2]), "=r"(r[3]) : "r"(addr));
}
__device__ __forceinline__ void ldmx2(uint32_t* r, uint32_t addr) {
    asm volatile("ldmatrix.sync.aligned.m8n8.x2.shared.b16 {%0,%1}, [%2];"
        : "=r"(r[0]), "=r"(r[1]) : "r"(addr));
}
__device__ __forceinline__ void ldmx4t(uint32_t* r, uint32_t addr) {
    asm volatile("ldmatrix.sync.aligned.m8n8.x4.trans.shared.b16 {%0,%1,%2,%3}, [%4];"
        : "=r"(r[0]), "=r"(r[1]), "=r"(r[2]), "=r"(r[3]) : "r"(addr));
}
__device__ __forceinline__ void mma16816(float* c, const uint32_t* a, const uint32_t* b) {
    asm volatile(
        "mma.sync.aligned.m16n8k16.row.col.f32.bf16.bf16.f32 "
        "{%0,%1,%2,%3}, {%4,%5,%6,%7}, {%8,%9}, {%0,%1,%2,%3};"
        : "+f"(c[0]), "+f"(c[1]), "+f"(c[2]), "+f"(c[3])
        : "r"(a[0]), "r"(a[1]), "r"(a[2]), "r"(a[3]), "r"(b[0]), "r"(b[1]));
}
__device__ __forceinline__ void cp16(uint32_t d, const void* s) {
    asm volatile("cp.async.ca.shared.global [%0], [%1], 16;" :: "r"(d), "l"(s));
}
__device__ __forceinline__ void pack_hilo(float x, float y, uint32_t& h, uint32_t& l) {
    __nv_bfloat162 hb = __floats2bfloat162_rn(x, y);
    float rx = x - __bfloat162float(hb.x);
    float ry = y - __bfloat162float(hb.y);
    __nv_bfloat162 lb = __floats2bfloat162_rn(rx, ry);
    h = *(uint32_t*)&hb;
    l = *(uint32_t*)&lb;
}

// ---------------- cumsum of seizure labels (per batch) ---------------------
__global__ void cumsum_kernel(const int* __restrict__ labels) {
    __shared__ int bufA[S_LEN], bufB[S_LEN];
    int b = blockIdx.x;
    for (int i = threadIdx.x; i < S_LEN; i += blockDim.x)
        bufA[i] = labels[b * S_LEN + i];
    __syncthreads();
    int* src = bufA; int* dst = bufB;
    for (int off = 1; off < S_LEN; off <<= 1) {
        for (int i = threadIdx.x; i < S_LEN; i += blockDim.x)
            dst[i] = src[i] + (i >= off ? src[i - off] : 0);
        __syncthreads();
        int* t = src; src = dst; dst = t;
    }
    for (int i = threadIdx.x; i < S_LEN; i += blockDim.x)
        g_cs[b * S_LEN + i] = src[i];
}

// ---------------- bf16 split helpers ---------------------------------------
__device__ __forceinline__ void split4(float4 v, uint32_t& h01, uint32_t& h23,
                                       uint32_t& l01, uint32_t& l23) {
    pack_hilo(v.x, v.y, h01, l01);
    pack_hilo(v.z, v.w, h23, l23);
}

__global__ void split_kernel(const float* __restrict__ in,
                             __nv_bfloat16* __restrict__ hi,
                             __nv_bfloat16* __restrict__ lo, int n4) {
    int i = blockIdx.x * blockDim.x + threadIdx.x;
    if (i >= n4) return;
    float4 v = ((const float4*)in)[i];
    uint32_t h01, h23, l01, l23;
    split4(v, h01, h23, l01, l23);
    *(uint2*)(hi + (size_t)i * 4) = make_uint2(h01, h23);
    *(uint2*)(lo + (size_t)i * 4) = make_uint2(l01, l23);
}

// ---------------- layernorm -> bf16 hi/lo -----------------------------------
__global__ void ln_kernel(const float* __restrict__ in, const float* __restrict__ w,
                          const float* __restrict__ bvec,
                          __nv_bfloat16* __restrict__ oh, __nv_bfloat16* __restrict__ ol) {
    int row = blockIdx.x;
    const float* x = in + (size_t)row * DIMN;
    int tid = threadIdx.x;

    float4 v0 = *(const float4*)(x + tid * 4);
    float4 v1 = *(const float4*)(x + 1024 + tid * 4);
    float s  = v0.x + v0.y + v0.z + v0.w + v1.x + v1.y + v1.z + v1.w;
    float ss = v0.x*v0.x + v0.y*v0.y + v0.z*v0.z + v0.w*v0.w
             + v1.x*v1.x + v1.y*v1.y + v1.z*v1.z + v1.w*v1.w;
    #pragma unroll
    for (int off = 16; off; off >>= 1) {
        s  += __shfl_xor_sync(0xffffffffu, s,  off);
        ss += __shfl_xor_sync(0xffffffffu, ss, off);
    }
    __shared__ float rs[8], rss[8];
    __shared__ float s_mu, s_rstd;
    int wid = tid >> 5, lane = tid & 31;
    if (!lane) { rs[wid] = s; rss[wid] = ss; }
    __syncthreads();
    if (tid == 0) {
        float S = 0.f, SS = 0.f;
        #pragma unroll
        for (int i = 0; i < 8; ++i) { S += rs[i]; SS += rss[i]; }
        float mu = S / DIMN;
        s_mu = mu;
        s_rstd = rsqrtf(SS / DIMN - mu * mu + 1e-5f);
    }
    __syncthreads();
    float mu = s_mu, rstd = s_rstd;

    size_t base = (size_t)row * DIMN;
    #pragma unroll
    for (int half = 0; half < 2; ++half) {
        int off = half * 1024 + tid * 4;
        float4 v = half ? v1 : v0;
        float4 w4 = *(const float4*)(w + off);
        float4 b4 = *(const float4*)(bvec + off);
        float4 r;
        r.x = (v.x - mu) * rstd * w4.x + b4.x;
        r.y = (v.y - mu) * rstd * w4.y + b4.y;
        r.z = (v.z - mu) * rstd * w4.z + b4.z;
        r.w = (v.w - mu) * rstd * w4.w + b4.w;
        uint32_t h01, h23, l01, l23;
        split4(r, h01, h23, l01, l23);
        *(uint2*)(oh + base + off) = make_uint2(h01, h23);
        *(uint2*)(ol + base + off) = make_uint2(l01, l23);
    }
}

// ---------------- mma.sync GEMM: C[M,N] = A[M,K] * B[N,K]^T -----------------
#define PITCH 80
#define TILE_B (128 * PITCH)
#define STAGE_B (4 * TILE_B)

__device__ __forceinline__ void cp_tile(uint32_t sdst, const __nv_bfloat16* __restrict__ g,
                                        int row0, int K, int k0) {
    int tid = threadIdx.x;
    const char* gb = (const char*)(g + (size_t)row0 * K + k0);
    size_t rb = (size_t)K * 2;
    #pragma unroll
    for (int j = 0; j < 2; ++j) {
        int lin = j * 256 + tid;
        int r = lin >> 2, c = lin & 3;
        cp16(sdst + r * PITCH + c * 16, gb + (size_t)r * rb + c * 16);
    }
}

__global__ __launch_bounds__(256)
void mma_gemm(const __nv_bfloat16* __restrict__ Ah, const __nv_bfloat16* __restrict__ Al,
              const __nv_bfloat16* __restrict__ Bh, const __nv_bfloat16* __restrict__ Bl,
              float* __restrict__ C, int M, int N, int K) {
    extern __shared__ char sm[];
    uint32_t sb = smem_to_u32(sm);
    int tid = threadIdx.x, lane = tid & 31, wid = tid >> 5;
    int wm = wid & 1, wn = wid >> 1;
    int row0 = blockIdx.y * 128, col0 = blockIdx.x * 128;

    float acc[4][4][4];
    #pragma unroll
    for (int i = 0; i < 4; ++i)
        #pragma unroll
        for (int j = 0; j < 4; ++j)
            #pragma unroll
            for (int q = 0; q < 4; ++q) acc[i][j][q] = 0.f;

    const int nst = K >> 5;

    cp_tile(sb,              Ah, row0, K, 0);
    cp_tile(sb + TILE_B,     Al, row0, K, 0);
    cp_tile(sb + 2 * TILE_B, Bh, col0, K, 0);
    cp_tile(sb + 3 * TILE_B, Bl, col0, K, 0);
    asm volatile("cp.async.commit_group;" ::: "memory");

    for (int i = 0; i < nst; ++i) {
        if (i + 1 < nst) {
            uint32_t st = sb + ((i + 1) & 1) * STAGE_B;
            int k0 = (i + 1) << 5;
            cp_tile(st,              Ah, row0, K, k0);
            cp_tile(st + TILE_B,     Al, row0, K, k0);
            cp_tile(st + 2 * TILE_B, Bh, col0, K, k0);
            cp_tile(st + 3 * TILE_B, Bl, col0, K, k0);
            asm volatile("cp.async.commit_group;" ::: "memory");
            asm volatile("cp.async.wait_group 1;" ::: "memory");
        } else {
            asm volatile("cp.async.wait_group 0;" ::: "memory");
        }
        __syncthreads();

        uint32_t st = sb + (i & 1) * STAGE_B;
        #pragma unroll
        for (int ks = 0; ks < 2; ++ks) {
            uint32_t ah[4][4], al[4][4], bh[4][2], bl[4][2];
            uint32_t abase = st + (wm * 64 + (lane & 15)) * PITCH
                           + (ks * 2 + (lane >> 4)) * 16;
            #pragma unroll
            for (int mi = 0; mi < 4; ++mi) ldmx4(ah[mi], abase + mi * 16 * PITCH);
            #pragma unroll
            for (int mi = 0; mi < 4; ++mi) ldmx4(al[mi], abase + TILE_B + mi * 16 * PITCH);
            uint32_t bbase = st + 2 * TILE_B + (wn * 32 + (lane & 7)) * PITCH
                           + ((lane >> 3) & 1) * 16 + ks * 32;
            #pragma unroll
            for (int ni = 0; ni < 4; ++ni) ldmx2(bh[ni], bbase + ni * 8 * PITCH);
            #pragma unroll
            for (int ni = 0; ni < 4; ++ni) ldmx2(bl[ni], bbase + TILE_B + ni * 8 * PITCH);
            #pragma unroll
            for (int mi = 0; mi < 4; ++mi)
                #pragma unroll
                for (int ni = 0; ni < 4; ++ni) {
                    mma16816(acc[mi][ni], ah[mi], bh[ni]);
                    mma16816(acc[mi][ni], ah[mi], bl[ni]);
                    mma16816(acc[mi][ni], al[mi], bh[ni]);
                }
        }
        __syncthreads();
    }

    int mrow = row0 + wm * 64 + (lane >> 2);
    int ncol = col0 + wn * 32 + (lane & 3) * 2;
    #pragma unroll
    for (int mi = 0; mi < 4; ++mi)
        #pragma unroll
        for (int ni = 0; ni < 4; ++ni) {
            float* p0 = C + (size_t)(mrow + mi * 16) * N + ncol + ni * 8;
            float* p1 = C + (size_t)(mrow + mi * 16 + 8) * N + ncol + ni * 8;
            *(float2*)p0 = make_float2(acc[mi][ni][0], acc[mi][ni][1]);
            *(float2*)p1 = make_float2(acc[mi][ni][2], acc[mi][ni][3]);
        }
}

// ---------------- RoPE + scale + bf16 split ---------------------------------
// one thread = 8 contiguous elems (4 rope pairs)
__global__ void rope_split(const float* __restrict__ src, const float* __restrict__ fr,
                           __nv_bfloat16* __restrict__ oh, __nv_bfloat16* __restrict__ ol,
                           int H, float scale) {
    int idx = blockIdx.x * blockDim.x + threadIdx.x;
    int i8 = idx & 15;
    int h  = (idx >> 4) % H;
    int bs = idx / (16 * H);
    int s  = bs & (S_LEN - 1);
    size_t base = ((size_t)bs * H + h) * HD + i8 * 8;
    float4 v0 = *(const float4*)(src + base);
    float4 v1 = *(const float4*)(src + base + 4);
    float e[8] = {v0.x, v0.y, v0.z, v0.w, v1.x, v1.y, v1.z, v1.w};
    uint32_t hw[4], lw[4];
    #pragma unroll
    for (int p = 0; p < 4; ++p) {
        int fi = i8 * 4 + p;
        float c  = fr[(s * 64 + fi) * 2 + 0];
        float sn = fr[(s * 64 + fi) * 2 + 1];
        float xr = e[2 * p], xi = e[2 * p + 1];
        float orr = (xr * c - xi * sn) * scale;
        float oii = (xr * sn + xi * c) * scale;
        pack_hilo(orr, oii, hw[p], lw[p]);
    }
    *(uint4*)(oh + base) = make_uint4(hw[0], hw[1], hw[2], hw[3]);
    *(uint4*)(ol + base) = make_uint4(lw[0], lw[1], lw[2], lw[3]);
}

// ---------------- tensor-core flash attention --------------------------------
// CTA: 64 q-rows x full HD; 4 warps, each 16 q-rows. K-tiles of 64, double-buffered.
#define APITCH 272
#define ATILE  (64 * APITCH)   // 17408 bytes

// load a 64x128 bf16 tile (rows = kv positions) into padded smem via cp.async
__device__ __forceinline__ void cp_kv(uint32_t dst, const __nv_bfloat16* __restrict__ g,
                                      int b, int kvh, int row0) {
    int tid = threadIdx.x;
    #pragma unroll
    for (int j = 0; j < 8; ++j) {
        int lin = j * 128 + tid;
        int r = lin >> 4, c = lin & 15;
        const __nv_bfloat16* s = g + (((size_t)(b * S_LEN + row0 + r)) * NKV + kvh) * HD + c * 8;
        cp16(dst + r * APITCH + c * 16, s);
    }
}

__global__ __launch_bounds__(128, 1)
void attn_kernel() {
    extern __shared__ char asm_[];
    uint32_t sb = smem_to_u32(asm_);
    const uint32_t smQh = sb;
    const uint32_t smQl = sb + ATILE;
    const uint32_t smKV = sb + 2 * ATILE;   // stage s: Kh,Kl,Vh,Vl each ATILE

    const int tid = threadIdx.x;
    const int lane = tid & 31, wid = tid >> 5;
    const int gid = lane >> 2, tig = lane & 3;
    const int q0 = blockIdx.x * 64;
    const int h  = blockIdx.y;
    const int b  = blockIdx.z;
    const int kvh = h >> 2;
    const int m0 = wid * 16;
    const int nkt = blockIdx.x + 1;

    // ---- prologue: Q tiles + KV stage 0 (group 0), KV stage 1 (group 1) ----
    #pragma unroll
    for (int j = 0; j < 8; ++j) {
        int lin = j * 128 + tid;
        int r = lin >> 4, c = lin & 15;
        size_t go = (((size_t)(b * S_LEN + q0 + r)) * NH + h) * HD + c * 8;
        cp16(smQh + r * APITCH + c * 16, g_qh + go);
        cp16(smQl + r * APITCH + c * 16, g_ql + go);
    }
    cp_kv(smKV,             g_kh, b, kvh, 0);
    cp_kv(smKV + ATILE,     g_kl, b, kvh, 0);
    cp_kv(smKV + 2 * ATILE, g_vh, b, kvh, 0);
    cp_kv(smKV + 3 * ATILE, g_vl, b, kvh, 0);
    asm volatile("cp.async.commit_group;" ::: "memory");
    if (nkt > 1) {
        uint32_t st = smKV + 4 * ATILE;
        cp_kv(st,             g_kh, b, kvh, 64);
        cp_kv(st + ATILE,     g_kl, b, kvh, 64);
        cp_kv(st + 2 * ATILE, g_vh, b, kvh, 64);
        cp_kv(st + 3 * ATILE, g_vl, b, kvh, 64);
        asm volatile("cp.async.commit_group;" ::: "memory");
    }

    const int qg0 = q0 + m0 + gid;   // row for c0,c1
    const int qg1 = qg0 + 8;         // row for c2,c3
    const int csq0 = (qg0 > 0) ? g_cs[b * S_LEN + qg0 - 1] : 0;
    const int csq1 = g_cs[b * S_LEN + qg1 - 1];   // qg1 >= 8 > 0 always

    float oacc[16][4];
    #pragma unroll
    for (int d = 0; d < 16; ++d)
        #pragma unroll
        for (int q = 0; q < 4; ++q) oacc[d][q] = 0.f;
    float mrow0 = -1e30f, mrow1 = -1e30f, lrow0 = 0.f, lrow1 = 0.f;

    for (int it = 0; it < nkt; ++it) {
        const int k0 = it * 64;
        if (it + 1 < nkt) asm volatile("cp.async.wait_group 1;" ::: "memory");
        else              asm volatile("cp.async.wait_group 0;" ::: "memory");
        __syncthreads();

        const uint32_t st  = smKV + (it & 1) * 4 * ATILE;
        const uint32_t sKh = st, sKl = st + ATILE, sVh = st + 2 * ATILE, sVl = st + 3 * ATILE;

        // ---- S = Q K^T (bf16-split, fp32 accum) ----
        float sacc[8][4];
        #pragma unroll
        for (int j = 0; j < 8; ++j)
            #pragma unroll
            for (int q = 0; q < 4; ++q) sacc[j][q] = 0.f;

        const uint32_t qoff = (m0 + (lane & 15)) * APITCH + (lane >> 4) * 16;
        const uint32_t koff = (lane & 7) * APITCH + ((lane >> 3) & 1) * 16;
        #pragma unroll
        for (int kk = 0; kk < 8; ++kk) {
            uint32_t qh[4], ql[4];
            ldmx4(qh, smQh + qoff + kk * 32);
            ldmx4(ql, smQl + qoff + kk * 32);
            #pragma unroll
            for (int j = 0; j < 8; ++j) {
                uint32_t kh[2], kl[2];
                ldmx2(kh, sKh + koff + j * 8 * APITCH + kk * 32);
                ldmx2(kl, sKl + koff + j * 8 * APITCH + kk * 32);
                mma16816(sacc[j], qh, kh);
                mma16816(sacc[j], qh, kl);
                mma16816(sacc[j], ql, kh);
            }
        }

        // ---- bias (pre-ictal) : only near-diagonal tiles can qualify ----
        if (k0 + 73 >= q0) {
            #pragma unroll
            for (int j = 0; j < 8; ++j) {
                int kg0 = k0 + j * 8 + tig * 2;
                int kg1 = kg0 + 1;
                int bi0 = kg0 + 10; if (bi0 > S_LEN - 1) bi0 = S_LEN - 1;
                int bi1 = kg1 + 10; if (bi1 > S_LEN - 1) bi1 = S_LEN - 1;
                int ck0 = g_cs[b * S_LEN + bi0];
                int ck1 = g_cs[b * S_LEN + bi1];
                if (kg0 + 10 >= qg0 && ck0 - csq0 > 0) sacc[j][0] += 2.0f;
                if (kg1 + 10 >= qg0 && ck1 - csq0 > 0) sacc[j][1] += 2.0f;
                if (kg0 + 10 >= qg1 && ck0 - csq1 > 0) sacc[j][2] += 2.0f;
                if (kg1 + 10 >= qg1 && ck1 - csq1 > 0) sacc[j][3] += 2.0f;
            }
        }
        // ---- causal mask : only diagonal tile ----
        if (k0 == q0) {
            #pragma unroll
            for (int j = 0; j < 8; ++j) {
                int kg0 = k0 + j * 8 + tig * 2;
                int kg1 = kg0 + 1;
                if (kg0 > qg0) sacc[j][0] = -1e9f;
                if (kg1 > qg0) sacc[j][1] = -1e9f;
                if (kg0 > qg1) sacc[j][2] = -1e9f;
                if (kg1 > qg1) sacc[j][3] = -1e9f;
            }
        }

        // ---- online softmax ----
        float mx0 = -1e30f, mx1 = -1e30f;
        #pragma unroll
        for (int j = 0; j < 8; ++j) {
            mx0 = fmaxf(mx0, fmaxf(sacc[j][0], sacc[j][1]));
            mx1 = fmaxf(mx1, fmaxf(sacc[j][2], sacc[j][3]));
        }
        mx0 = fmaxf(mx0, __shfl_xor_sync(0xffffffffu, mx0, 1));
        mx0 = fmaxf(mx0, __shfl_xor_sync(0xffffffffu, mx0, 2));
        mx1 = fmaxf(mx1, __shfl_xor_sync(0xffffffffu, mx1, 1));
        mx1 = fmaxf(mx1, __shfl_xor_sync(0xffffffffu, mx1, 2));
        float mn0 = fmaxf(mrow0, mx0), mn1 = fmaxf(mrow1, mx1);
        float a0 = __expf(mrow0 - mn0), a1 = __expf(mrow1 - mn1);
        mrow0 = mn0; mrow1 = mn1;
        float sum0 = 0.f, sum1 = 0.f;
        #pragma unroll
        for (int j = 0; j < 8; ++j) {
            sacc[j][0] = __expf(sacc[j][0] - mn0); sum0 += sacc[j][0];
            sacc[j][1] = __expf(sacc[j][1] - mn0); sum0 += sacc[j][1];
            sacc[j][2] = __expf(sacc[j][2] - mn1); sum1 += sacc[j][2];
            sacc[j][3] = __expf(sacc[j][3] - mn1); sum1 += sacc[j][3];
        }
        sum0 += __shfl_xor_sync(0xffffffffu, sum0, 1);
        sum0 += __shfl_xor_sync(0xffffffffu, sum0, 2);
        sum1 += __shfl_xor_sync(0xffffffffu, sum1, 1);
        sum1 += __shfl_xor_sync(0xffffffffu, sum1, 2);
        lrow0 = lrow0 * a0 + sum0;
        lrow1 = lrow1 * a1 + sum1;
        #pragma unroll
        for (int d = 0; d < 16; ++d) {
            oacc[d][0] *= a0; oacc[d][1] *= a0;
            oacc[d][2] *= a1; oacc[d][3] *= a1;
        }

        // ---- P fragments (hi/lo) ----
        uint32_t aph[4][4], apl[4][4];
        #pragma unroll
        for (int t = 0; t < 4; ++t) {
            int j0 = 2 * t, j1 = 2 * t + 1;
            pack_hilo(sacc[j0][0], sacc[j0][1], aph[t][0], apl[t][0]);
            pack_hilo(sacc[j0][2], sacc[j0][3], aph[t][1], apl[t][1]);
            pack_hilo(sacc[j1][0], sacc[j1][1], aph[t][2], apl[t][2]);
            pack_hilo(sacc[j1][2], sacc[j1][3], aph[t][3], apl[t][3]);
        }

        // ---- O += P V ----
        const uint32_t voff = (lane & 15) * APITCH + (lane >> 4) * 16;
        #pragma unroll
        for (int t = 0; t < 4; ++t) {
            #pragma unroll
            for (int dn2 = 0; dn2 < 8; ++dn2) {
                uint32_t vh[4], vl[4];
                uint32_t va = voff + t * 16 * APITCH + dn2 * 32;
                ldmx4t(vh, sVh + va);
                ldmx4t(vl, sVl + va);
                mma16816(oacc[2 * dn2],     aph[t], vh);
                mma16816(oacc[2 * dn2],     aph[t], vl);
                mma16816(oacc[2 * dn2],     apl[t], vh);
                mma16816(oacc[2 * dn2 + 1], aph[t], vh + 2);
                mma16816(oacc[2 * dn2 + 1], aph[t], vl + 2);
                mma16816(oacc[2 * dn2 + 1], apl[t], vh + 2);
            }
        }
        __syncthreads();

        // prefetch stage it+2
        if (it + 2 < nkt) {
            uint32_t pst = smKV + (it & 1) * 4 * ATILE;
            int row0 = (it + 2) * 64;
            cp_kv(pst,             g_kh, b, kvh, row0);
            cp_kv(pst + ATILE,     g_kl, b, kvh, row0);
            cp_kv(pst + 2 * ATILE, g_vh, b, kvh, row0);
            cp_kv(pst + 3 * ATILE, g_vl, b, kvh, row0);
            asm volatile("cp.async.commit_group;" ::: "memory");
        }
    }

    // ---- epilogue ----
    float il0 = 1.0f / lrow0, il1 = 1.0f / lrow1;
    size_t b0 = (((size_t)(b * S_LEN + qg0)) * NH + h) * HD + tig * 2;
    size_t b1 = (((size_t)(b * S_LEN + qg1)) * NH + h) * HD + tig * 2;
    #pragma unroll
    for (int d = 0; d < 16; ++d) {
        *(float2*)(g_ao + b0 + d * 8) = make_float2(oacc[d][0] * il0, oacc[d][1] * il0);
        *(float2*)(g_ao + b1 + d * 8) = make_float2(oacc[d][2] * il1, oacc[d][3] * il1);
    }
}

// ---------------- launch ----------------------------------------------------
extern "C" void kernel_launch(void* const* d_in, const int* in_sizes, int n_in,
                              void* d_out, int out_size) {
    const float* x      = (const float*)d_in[0];
    const float* freqs  = (const float*)d_in[2];
    const int*   labels = (const int*)d_in[4];
    const float* wq     = (const float*)d_in[5];
    const float* wk     = (const float*)d_in[6];
    const float* wv     = (const float*)d_in[7];
    const float* wo     = (const float*)d_in[8];
    const float* ln1w   = (const float*)d_in[9];
    const float* ln1b   = (const float*)d_in[10];
    const float* ln2w   = (const float*)d_in[11];
    const float* ln2b   = (const float*)d_in[12];
    float* out = (float*)d_out;

    __nv_bfloat16 *xnh, *xnl, *wqh, *wql, *wkh, *wkl, *wvh, *wvl, *woh, *wol;
    __nv_bfloat16 *vh, *vl;
    float *q, *k, *v, *ao;
    cudaGetSymbolAddress((void**)&xnh, g_xn_h);
    cudaGetSymbolAddress((void**)&xnl, g_xn_l);
    cudaGetSymbolAddress((void**)&wqh, g_wq_h);
    cudaGetSymbolAddress((void**)&wql, g_wq_l);
    cudaGetSymbolAddress((void**)&wkh, g_wk_h);
    cudaGetSymbolAddress((void**)&wkl, g_wk_l);
    cudaGetSymbolAddress((void**)&wvh, g_wv_h);
    cudaGetSymbolAddress((void**)&wvl, g_wv_l);
    cudaGetSymbolAddress((void**)&woh, g_wo_h);
    cudaGetSymbolAddress((void**)&wol, g_wo_l);
    cudaGetSymbolAddress((void**)&q,   g_q);
    cudaGetSymbolAddress((void**)&k,   g_k);
    cudaGetSymbolAddress((void**)&v,   g_v);
    cudaGetSymbolAddress((void**)&vh,  g_vh);
    cudaGetSymbolAddress((void**)&vl,  g_vl);
    cudaGetSymbolAddress((void**)&ao,  g_ao);

    __nv_bfloat16 *qh, *ql, *kh, *kl;
    cudaGetSymbolAddress((void**)&qh, g_qh);
    cudaGetSymbolAddress((void**)&ql, g_ql);
    cudaGetSymbolAddress((void**)&kh, g_kh);
    cudaGetSymbolAddress((void**)&kl, g_kl);

    cumsum_kernel<<<2, 1024>>>(labels);

    split_kernel<<<(DIMN * DIMN / 4 + 255) / 256, 256>>>(wq, wqh, wql, DIMN * DIMN / 4);
    split_kernel<<<(512 * DIMN / 4 + 255) / 256, 256>>>(wk, wkh, wkl, 512 * DIMN / 4);
    split_kernel<<<(512 * DIMN / 4 + 255) / 256, 256>>>(wv, wvh, wvl, 512 * DIMN / 4);
    split_kernel<<<(DIMN * DIMN / 4 + 255) / 256, 256>>>(wo, woh, wol, DIMN * DIMN / 4);

    ln_kernel<<<ROWS, 256>>>(x, ln1w, ln1b, xnh, xnl);

    size_t gemm_smem = 2 * STAGE_B;
    cudaFuncSetAttribute(mma_gemm, cudaFuncAttributeMaxDynamicSharedMemorySize, (int)gemm_smem);

    dim3 gq(DIMN / 128, ROWS / 128);
    dim3 gkv(512 / 128, ROWS / 128);
    mma_gemm<<<gq, 256, gemm_smem>>>(xnh, xnl, wqh, wql, q, ROWS, DIMN, DIMN);
    mma_gemm<<<gkv, 256, gemm_smem>>>(xnh, xnl, wkh, wkl, k, ROWS, 512, DIMN);
    mma_gemm<<<gkv, 256, gemm_smem>>>(xnh, xnl, wvh, wvl, v, ROWS, 512, DIMN);

    const float qscale = 0.08838834764831845f;   // 1/sqrt(128)
    rope_split<<<(ROWS * NH * 16) / 256, 256>>>(q, freqs, qh, ql, NH, qscale);
    rope_split<<<(ROWS * NKV * 16) / 256, 256>>>(k, freqs, kh, kl, NKV, 1.0f);
    split_kernel<<<(ROWS * 512 / 4 + 255) / 256, 256>>>(v, vh, vl, ROWS * 512 / 4);

    size_t attn_smem = 10 * ATILE;   // 174080
    cudaFuncSetAttribute(attn_kernel, cudaFuncAttributeMaxDynamicSharedMemorySize,
                         (int)attn_smem);
    attn_kernel<<<dim3(S_LEN / 64, NH, 2), 128, attn_smem>>>();

    ln_kernel<<<ROWS, 256>>>(ao, ln2w, ln2b, xnh, xnl);
    mma_gemm<<<gq, 256, gemm_smem>>>(xnh, xnl, woh, wol, out, ROWS, DIMN, DIMN);
}